// round 10
// baseline (speedup 1.0000x reference)
#include <cuda_runtime.h>

#define HH 128
#define WW 256
#define SS 12
#define CC 32
#define BAND 74
#define HW (HH * WW)
#define WP 264
#define HP 130
#define PLANE (HP * WP)

// Band pair table with baked scale: g_band2[(h*BAND+b)*WW + w] =
//   (C*tab[x0], C*tab[x0+1]),  x0 = w+1-b,  C = 7/32 * log2(e).
// Zero where x out of [0,W). b rows 1..73 valid. 16B-aligned for uint4 copy.
__device__ __align__(16) float2 g_band2[HH * BAND * WW];   // 19.4 MB
// Padded noise ping-pong; zero borders (zero-init; only interior written).
__device__ float g_noiseA[SS * PLANE];
__device__ float g_noiseB[SS * PLANE];
__device__ float2 g_mdsv[HW];                    // (max(min,0), search/13)

#define FMA2(d, a, b, c) \
    asm("fma.rn.f32x2 %0, %1, %2, %3;" : "=l"(d) : "l"(a), "l"(b), "l"(c))
#define PACK2(out, v) \
    asm("mov.b64 %0, {%1, %1};" : "=l"(out) : "r"(__float_as_uint(v)))
#define UNPACK2(lo, hi, in) \
    asm("mov.b64 {%0, %1}, %2;" : "=r"(lo), "=r"(hi) : "l"(in))

__device__ __forceinline__ float ex2(float x) {
    float r; asm("ex2.approx.f32 %0, %1;" : "=f"(r) : "f"(x)); return r;
}
__device__ __forceinline__ float rcp(float x) {
    float r; asm("rcp.approx.f32 %0, %1;" : "=f"(r) : "f"(x)); return r;
}

// ---------------------------------------------------------------------------
// Fused front kernel (identical to R8, known good). blockIdx.x 0,1: band GEMM
// halves. blockIdx.x 2: prep. grid (3, HH), 192 threads.
// ---------------------------------------------------------------------------
__global__ __launch_bounds__(192) void front_kernel(
    const float* __restrict__ left, const float* __restrict__ right,
    const float* __restrict__ minD, const float* __restrict__ maxD,
    const float* __restrict__ noise) {
    const int h = blockIdx.y;
    const int tid = threadIdx.x;

    if (blockIdx.x == 2) {
        for (int i = tid; i < SS * WW; i += 192) {
            int s = i >> 8, w = i & 255;
            g_noiseA[s * PLANE + (h + 1) * WP + w + 1] = noise[s * HW + h * WW + w];
        }
        for (int w = tid; w < WW; w += 192) {
            int pix = h * WW + w;
            float md = fmaxf(minD[pix], 0.0f);
            float Md = fmaxf(maxD[pix], 0.0f);
            g_mdsv[pix] = make_float2(md, (Md - md) * (1.0f / (float)(SS + 1)));
        }
        return;
    }

    __shared__ float pool[12288];
    float (*As)[128] = (float(*)[128])pool;
    float (*Rs)[WW]  = (float(*)[WW])(pool + 4096);
    float (*Sb)[129] = (float(*)[129])pool;   // aliases, post-GEMM

    const int wbase = blockIdx.x * 128;

    for (int i = tid; i < CC * 128; i += 192) {
        int c = i >> 7, wl = i & 127;
        As[c][wl] = left[(c * HH + h) * WW + wbase + wl];
    }
    for (int i = tid; i < CC * WW; i += 192) {
        int c = i >> 8, x = i & 255;
        Rs[c][x] = right[(c * HH + h) * WW + x];
    }
    __syncthreads();

    const int tw = tid / 12;
    const int j  = tid % 12;
    const int twg = (wbase >> 3) + tw;
    const int txg = twg - 9 + j;
    const bool active = (j < 11) && (txg >= 0) && (txg <= 31);

    const int wl = tw * 8;
    const int x  = txg * 8;

    unsigned long long acc2[8][4];
    #pragma unroll
    for (int i = 0; i < 8; i++)
        #pragma unroll
        for (int q = 0; q < 4; q++) acc2[i][q] = 0ULL;

    if (active) {
        #pragma unroll 8
        for (int k = 0; k < CC; k++) {
            float a[8];
            *(float4*)&a[0] = *(const float4*)&As[k][wl];
            *(float4*)&a[4] = *(const float4*)&As[k][wl + 4];
            ulonglong2 t0 = *(const ulonglong2*)&Rs[k][x];
            ulonglong2 t1 = *(const ulonglong2*)&Rs[k][x + 4];
            unsigned long long b2[4] = {t0.x, t0.y, t1.x, t1.y};
            #pragma unroll
            for (int i = 0; i < 8; i++) {
                unsigned long long a2;
                PACK2(a2, a[i]);
                #pragma unroll
                for (int q = 0; q < 4; q++)
                    FMA2(acc2[i][q], a2, b2[q], acc2[i][q]);
            }
        }
    }
    __syncthreads();

    if (active) {
        const int xl = x - wbase;
        #pragma unroll
        for (int i = 0; i < 8; i++) {
            #pragma unroll
            for (int q = 0; q < 8; q++) {
                unsigned lo, hi;
                UNPACK2(lo, hi, acc2[i][q >> 1]);
                float v = __uint_as_float((q & 1) ? hi : lo);
                int b = wl + i + 1 - xl - q;
                if (b >= 0 && b <= 73) Sb[b][wl + i] = v;
            }
        }
    }
    __syncthreads();

    const float Cs = 0.21875f * 1.4426950408889634f;   // 7/32 * log2(e)
    float2* dst = g_band2 + h * BAND * WW + wbase;
    for (int i2 = tid; i2 < 73 * 128; i2 += 192) {
        int b = (i2 >> 7) + 1;
        int wli = i2 & 127;
        int x0 = wbase + wli + 1 - b;
        float v0 = (x0 >= 0) ? Cs * Sb[b][wli] : 0.0f;
        float v1 = (x0 >= -1 && x0 <= 254) ? Cs * Sb[b - 1][wli] : 0.0f;
        dst[b * WW + wli] = make_float2(v0, v1);
    }
}

// ---------------------------------------------------------------------------
// One PatchMatch pass. Block = 64 pixels x 6 sample-groups (2 samples each);
// the block's band slice (74x64 float2 = 37.9 KB) is staged in smem, so every
// tap is one conflict-free 8B LDS (bank pair = wl%32, independent of b0).
// grid (4, HH), block (64,6). Flow: P0(H) A->B, P1(V) B->A, P2(H) A->B,
// P3(V) B->disp.
// ---------------------------------------------------------------------------
template<bool HORIZ, bool LAST>
__global__ __launch_bounds__(384) void pm_pass_kernel(float* __restrict__ disp_out) {
    __shared__ __align__(16) float2 sband[BAND][64];

    const int wl = threadIdx.x;                 // 0..63
    const int w0 = blockIdx.x * 64;
    const int w  = w0 + wl;
    const int h  = blockIdx.y;
    const int s0 = threadIdx.y;                 // samples s0, s0+6
    const int tid = threadIdx.x + 64 * threadIdx.y;
    const int pix = h * WW + w;

    // --- coalesced slice copy: 74 rows x 32 uint4 (16B) each ---
    {
        const float2* srow = g_band2 + h * (BAND * WW) + w0;
        for (int idx = tid; idx < BAND * 32; idx += 384) {
            int b = idx >> 5, c = idx & 31;
            ((uint4*)&sband[b][0])[c] = *(const uint4*)(srow + b * WW + c * 2);
        }
    }

    const float* __restrict__ nin  = HORIZ ? g_noiseA : g_noiseB;
    float*       __restrict__ nout = HORIZ ? g_noiseB : g_noiseA;

    const float2 ms = __ldg(&g_mdsv[pix]);
    const float sv = ms.y;
    const float fw = (float)w;

    // --- batch noise loads (overlap with smem copy latency) ---
    const int pp0 = s0 * PLANE + (h + 1) * WP + (w + 1);
    float np[2][3];
    #pragma unroll
    for (int u = 0; u < 2; u++) {
        const int pp = pp0 + u * 6 * PLANE;
        np[u][1] = __ldg(nin + pp);
        if (HORIZ) {
            np[u][0] = __ldg(nin + pp - 1);
            np[u][2] = __ldg(nin + pp + 1);
        } else {
            np[u][0] = __ldg(nin + pp - WP);
            np[u][2] = __ldg(nin + pp + WP);
        }
    }

    __syncthreads();

    const int wp1 = w + 1;
    float xs[2][3], frac[2][3];
    float2 dp[2][3];
    #pragma unroll
    for (int u = 0; u < 2; u++) {
        const float wim = fw - fmaf(sv, (float)(s0 + u * 6 + 1), ms.x);
        #pragma unroll
        for (int c = 0; c < 3; c++) {
            xs[u][c] = fmaf(np[u][c], -sv, wim);
            int k0 = __float2int_rd(xs[u][c]);
            frac[u][c] = xs[u][c] - (float)k0;
            int b0 = wp1 - k0;
            b0 = min(max(b0, 1), BAND - 1);
            dp[u][c] = sband[b0][wl];
        }
    }

    #pragma unroll
    for (int u = 0; u < 2; u++) {
        float e[3];
        #pragma unroll
        for (int c = 0; c < 3; c++)
            e[c] = ex2(fmaf(dp[u][c].y - dp[u][c].x, frac[u][c], dp[u][c].x));
        const float rZ = rcp(e[0] + e[1] + e[2]);
        const int s = s0 + u * 6;
        if (LAST) {
            float d = e[0] * (fw - xs[u][0]) + e[1] * (fw - xs[u][1])
                    + e[2] * (fw - xs[u][2]);
            disp_out[s * HW + pix] = d * rZ;
        } else {
            nout[pp0 + u * 6 * PLANE] =
                (e[0] * np[u][0] + e[1] * np[u][1] + e[2] * np[u][2]) * rZ;
        }
    }
}

extern "C" void kernel_launch(void* const* d_in, const int* in_sizes, int n_in,
                              void* d_out, int out_size) {
    const float* left  = (const float*)d_in[0];
    const float* right = (const float*)d_in[1];
    const float* minD  = (const float*)d_in[2];
    const float* maxD  = (const float*)d_in[3];
    const float* noise = (const float*)d_in[4];
    float* disp = (float*)d_out;

    front_kernel<<<dim3(3, HH), 192>>>(left, right, minD, maxD, noise);

    dim3 grid(4, HH), blk(64, 6);
    pm_pass_kernel<true,  false><<<grid, blk>>>(disp);  // P0 H: A->B
    pm_pass_kernel<false, false><<<grid, blk>>>(disp);  // P1 V: B->A
    pm_pass_kernel<true,  false><<<grid, blk>>>(disp);  // P2 H: A->B
    pm_pass_kernel<false, true ><<<grid, blk>>>(disp);  // P3 V: B->disp
}

// round 11
// speedup vs baseline: 1.1837x; 1.1837x over previous
#include <cuda_runtime.h>
#include <cuda_fp16.h>

#define HH 128
#define WW 256
#define SS 12
#define CC 32
#define BAND 74
#define HW (HH * WW)
#define WP 264
#define HP 130
#define PLANE (HP * WP)

// Band pair table, fp16 with baked scale:
//   g_band2h[(h*BAND+b)*WW + w] = half2(C*tab[x0], C*tab[x0+1]),
//   x0 = w+1-b, C = 7/32*log2(e). Zero where x out of [0,W). b rows 1..73.
// Accessed ONLY with 4-byte loads/stores (half2 is 4B-aligned).
__device__ __half2 g_band2h[HH * BAND * WW];     // 9.7 MB
// Padded noise ping-pong; zero borders (zero-init; only interior written).
__device__ float g_noiseA[SS * PLANE];
__device__ float g_noiseB[SS * PLANE];
__device__ float2 g_mdsv[HW];                    // (max(min,0), search/13)

#define FMA2(d, a, b, c) \
    asm("fma.rn.f32x2 %0, %1, %2, %3;" : "=l"(d) : "l"(a), "l"(b), "l"(c))
#define PACK2(out, v) \
    asm("mov.b64 %0, {%1, %1};" : "=l"(out) : "r"(__float_as_uint(v)))
#define UNPACK2(lo, hi, in) \
    asm("mov.b64 {%0, %1}, %2;" : "=r"(lo), "=r"(hi) : "l"(in))

__device__ __forceinline__ float ex2(float x) {
    float r; asm("ex2.approx.f32 %0, %1;" : "=f"(r) : "f"(x)); return r;
}
__device__ __forceinline__ float rcp(float x) {
    float r; asm("rcp.approx.f32 %0, %1;" : "=f"(r) : "f"(x)); return r;
}

// ---------------------------------------------------------------------------
// Fused front kernel. blockIdx.x 0,1: band GEMM halves. blockIdx.x 2: prep.
// grid (3, HH), 192 threads.
// ---------------------------------------------------------------------------
__global__ __launch_bounds__(192) void front_kernel(
    const float* __restrict__ left, const float* __restrict__ right,
    const float* __restrict__ minD, const float* __restrict__ maxD,
    const float* __restrict__ noise) {
    const int h = blockIdx.y;
    const int tid = threadIdx.x;

    if (blockIdx.x == 2) {
        for (int i = tid; i < SS * WW; i += 192) {
            int s = i >> 8, w = i & 255;
            g_noiseA[s * PLANE + (h + 1) * WP + w + 1] = noise[s * HW + h * WW + w];
        }
        for (int w = tid; w < WW; w += 192) {
            int pix = h * WW + w;
            float md = fmaxf(minD[pix], 0.0f);
            float Md = fmaxf(maxD[pix], 0.0f);
            g_mdsv[pix] = make_float2(md, (Md - md) * (1.0f / (float)(SS + 1)));
        }
        return;
    }

    __shared__ float pool[12288];
    float (*As)[128] = (float(*)[128])pool;
    float (*Rs)[WW]  = (float(*)[WW])(pool + 4096);
    float (*Sb)[129] = (float(*)[129])pool;   // aliases, post-GEMM

    const int wbase = blockIdx.x * 128;

    for (int i = tid; i < CC * 128; i += 192) {
        int c = i >> 7, wl = i & 127;
        As[c][wl] = left[(c * HH + h) * WW + wbase + wl];
    }
    for (int i = tid; i < CC * WW; i += 192) {
        int c = i >> 8, x = i & 255;
        Rs[c][x] = right[(c * HH + h) * WW + x];
    }
    __syncthreads();

    const int tw = tid / 12;
    const int j  = tid % 12;
    const int twg = (wbase >> 3) + tw;
    const int txg = twg - 9 + j;
    const bool active = (j < 11) && (txg >= 0) && (txg <= 31);

    const int wl = tw * 8;
    const int x  = txg * 8;

    unsigned long long acc2[8][4];
    #pragma unroll
    for (int i = 0; i < 8; i++)
        #pragma unroll
        for (int q = 0; q < 4; q++) acc2[i][q] = 0ULL;

    if (active) {
        #pragma unroll 8
        for (int k = 0; k < CC; k++) {
            float a[8];
            *(float4*)&a[0] = *(const float4*)&As[k][wl];
            *(float4*)&a[4] = *(const float4*)&As[k][wl + 4];
            ulonglong2 t0 = *(const ulonglong2*)&Rs[k][x];
            ulonglong2 t1 = *(const ulonglong2*)&Rs[k][x + 4];
            unsigned long long b2[4] = {t0.x, t0.y, t1.x, t1.y};
            #pragma unroll
            for (int i = 0; i < 8; i++) {
                unsigned long long a2;
                PACK2(a2, a[i]);
                #pragma unroll
                for (int q = 0; q < 4; q++)
                    FMA2(acc2[i][q], a2, b2[q], acc2[i][q]);
            }
        }
    }
    __syncthreads();

    if (active) {
        const int xl = x - wbase;
        #pragma unroll
        for (int i = 0; i < 8; i++) {
            #pragma unroll
            for (int q = 0; q < 8; q++) {
                unsigned lo, hi;
                UNPACK2(lo, hi, acc2[i][q >> 1]);
                float v = __uint_as_float((q & 1) ? hi : lo);
                int b = wl + i + 1 - xl - q;
                if (b >= 0 && b <= 73) Sb[b][wl + i] = v;
            }
        }
    }
    __syncthreads();

    const float Cs = 0.21875f * 1.4426950408889634f;   // 7/32 * log2(e)
    __half2* dst = g_band2h + h * BAND * WW + wbase;
    for (int i2 = tid; i2 < 73 * 128; i2 += 192) {
        int b = (i2 >> 7) + 1;
        int wli = i2 & 127;
        int x0 = wbase + wli + 1 - b;
        float v0 = (x0 >= 0) ? Cs * Sb[b][wli] : 0.0f;
        float v1 = (x0 >= -1 && x0 <= 254) ? Cs * Sb[b - 1][wli] : 0.0f;
        dst[b * WW + wli] = __floats2half2_rn(v0, v1);   // 4B store
    }
}

// ---------------------------------------------------------------------------
// One PatchMatch pass (R8 shape): thread = (pixel, samples s0 and s0+6),
// direct 4B __ldg gathers from the fp16 pair table. Single wave:
// grid (4, HH) x block (64,6) = 6144 warps.
// Flow: P0(H) A->B, P1(V) B->A, P2(H) A->B, P3(V) B->disp.
// ---------------------------------------------------------------------------
template<bool HORIZ, bool LAST>
__global__ __launch_bounds__(384) void pm_pass_kernel(float* __restrict__ disp_out) {
    const int w = blockIdx.x * 64 + threadIdx.x;
    const int h = blockIdx.y;
    const int s0 = threadIdx.y;                 // samples s0, s0+6
    const int pix = h * WW + w;

    const float* __restrict__ nin  = HORIZ ? g_noiseA : g_noiseB;
    float*       __restrict__ nout = HORIZ ? g_noiseB : g_noiseA;

    const float2 ms = __ldg(&g_mdsv[pix]);
    const float sv = ms.y;
    const float fw = (float)w;

    // --- batch all loads up front (1 + 6 LDG, independent) ---
    const int pp0 = s0 * PLANE + (h + 1) * WP + (w + 1);
    float np[2][3];
    #pragma unroll
    for (int u = 0; u < 2; u++) {
        const int pp = pp0 + u * 6 * PLANE;
        np[u][1] = __ldg(nin + pp);
        if (HORIZ) {
            np[u][0] = __ldg(nin + pp - 1);
            np[u][2] = __ldg(nin + pp + 1);
        } else {
            np[u][0] = __ldg(nin + pp - WP);
            np[u][2] = __ldg(nin + pp + WP);
        }
    }

    const __half2* __restrict__ brow = g_band2h + h * (BAND * WW) + w;
    const int wp1 = w + 1;

    // --- 6 independent 4B gathers ---
    float xs[2][3], frac[2][3];
    __half2 dph[2][3];
    #pragma unroll
    for (int u = 0; u < 2; u++) {
        const float wim = fw - fmaf(sv, (float)(s0 + u * 6 + 1), ms.x);
        #pragma unroll
        for (int c = 0; c < 3; c++) {
            xs[u][c] = fmaf(np[u][c], -sv, wim);
            int k0 = __float2int_rd(xs[u][c]);
            frac[u][c] = xs[u][c] - (float)k0;
            int b0 = wp1 - k0;
            b0 = min(max(b0, 1), BAND - 1);
            dph[u][c] = __ldg(brow + b0 * WW);
        }
    }

    // --- softmax + outputs ---
    #pragma unroll
    for (int u = 0; u < 2; u++) {
        float e[3];
        #pragma unroll
        for (int c = 0; c < 3; c++) {
            float2 d = __half22float2(dph[u][c]);
            e[c] = ex2(fmaf(d.y - d.x, frac[u][c], d.x));
        }
        const float rZ = rcp(e[0] + e[1] + e[2]);
        const int s = s0 + u * 6;
        if (LAST) {
            float d = e[0] * (fw - xs[u][0]) + e[1] * (fw - xs[u][1])
                    + e[2] * (fw - xs[u][2]);
            disp_out[s * HW + pix] = d * rZ;
        } else {
            nout[pp0 + u * 6 * PLANE] =
                (e[0] * np[u][0] + e[1] * np[u][1] + e[2] * np[u][2]) * rZ;
        }
    }
}

extern "C" void kernel_launch(void* const* d_in, const int* in_sizes, int n_in,
                              void* d_out, int out_size) {
    const float* left  = (const float*)d_in[0];
    const float* right = (const float*)d_in[1];
    const float* minD  = (const float*)d_in[2];
    const float* maxD  = (const float*)d_in[3];
    const float* noise = (const float*)d_in[4];
    float* disp = (float*)d_out;

    front_kernel<<<dim3(3, HH), 192>>>(left, right, minD, maxD, noise);

    dim3 grid(4, HH), blk(64, 6);
    pm_pass_kernel<true,  false><<<grid, blk>>>(disp);  // P0 H: A->B
    pm_pass_kernel<false, false><<<grid, blk>>>(disp);  // P1 V: B->A
    pm_pass_kernel<true,  false><<<grid, blk>>>(disp);  // P2 H: A->B
    pm_pass_kernel<false, true ><<<grid, blk>>>(disp);  // P3 V: B->disp
}